// round 1
// baseline (speedup 1.0000x reference)
#include <cuda_runtime.h>

#define FULL 0xffffffffu

// Scratch for the per-token PauliZ expectations (qlayer output), [B*S*E] = 131072 floats.
__device__ float g_q[4 * 512 * 64];

__device__ __forceinline__ float2 mk2(float x, float y) { float2 v; v.x = x; v.y = y; return v; }

// ---------- 1-qubit gates ----------
// State index i = lane*8 + r. Wire w has bit position p = 7-w (stride 2^p).
// p in {0,1,2}  -> register-pair op (stride 1<<p within the 8 per-thread amps)
// p in {3..7}   -> cross-lane op (shfl_xor mask 1<<(p-3))

__device__ __forceinline__ void rx_xlane(float2 a[8], int m, float c, float s) {
#pragma unroll
    for (int r = 0; r < 8; r++) {
        float px = __shfl_xor_sync(FULL, a[r].x, m);
        float py = __shfl_xor_sync(FULL, a[r].y, m);
        // a' = c*a + (-i s)*partner  (same formula on both sides of the pair)
        float nx = c * a[r].x + s * py;
        float ny = c * a[r].y - s * px;
        a[r].x = nx; a[r].y = ny;
    }
}

template <int D>
__device__ __forceinline__ void rx_inlane(float2 a[8], float c, float s) {
#pragma unroll
    for (int r = 0; r < 8; r++) {
        if (r & D) continue;
        float2 a0 = a[r], a1 = a[r + D];
        a[r]     = mk2(c * a0.x + s * a1.y, c * a0.y - s * a1.x);
        a[r + D] = mk2(c * a1.x + s * a0.y, c * a1.y - s * a0.x);
    }
}

template <int W>
__device__ __forceinline__ void apply_rx(float2 a[8], float c, float s) {
    constexpr int p = 7 - W;
    if constexpr (p >= 3) {
        rx_xlane(a, 1 << (p - 3), c, s);
    } else {
        rx_inlane<(1 << p)>(a, c, s);
    }
}

// RZ: amp *= e^{-i theta/2} if bit==0 else e^{+i theta/2}
template <int W>
__device__ __forceinline__ void apply_rz(float2 a[8], int lane, float c, float s) {
    constexpr int p = 7 - W;
    if constexpr (p >= 3) {
        float se = (lane & (1 << (p - 3))) ? s : -s;
#pragma unroll
        for (int r = 0; r < 8; r++) {
            float nx = c * a[r].x - se * a[r].y;
            float ny = c * a[r].y + se * a[r].x;
            a[r].x = nx; a[r].y = ny;
        }
    } else {
#pragma unroll
        for (int r = 0; r < 8; r++) {
            float se = (r & (1 << p)) ? s : -s;
            float nx = c * a[r].x - se * a[r].y;
            float ny = c * a[r].y + se * a[r].x;
            a[r].x = nx; a[r].y = ny;
        }
    }
}

__device__ __forceinline__ void swap2(float2 &u, float2 &v) { float2 t = u; u = v; v = t; }

// CNOT chain: (0->1),(1->2),...,(6->7),(7->0) applied sequentially.
__device__ __forceinline__ void cnot_chain(float2 a[8], int lane) {
    // (w, w+1) for w = 0..3: ctrl lane bit (4-w), tgt lane bit (3-w)
#pragma unroll
    for (int k = 4; k >= 1; k--) {
        bool cb = (lane >> k) & 1;
        int tm = 1 << (k - 1);
#pragma unroll
        for (int r = 0; r < 8; r++) {
            float px = __shfl_xor_sync(FULL, a[r].x, tm);
            float py = __shfl_xor_sync(FULL, a[r].y, tm);
            a[r].x = cb ? px : a[r].x;
            a[r].y = cb ? py : a[r].y;
        }
    }
    // (4 -> 5): ctrl lane bit 0, tgt r bit 2  (swap a[r] <-> a[r+4] when lane odd)
    {
        bool cb = lane & 1;
#pragma unroll
        for (int r = 0; r < 4; r++) {
            float2 lo = a[r], hi = a[r + 4];
            a[r].x     = cb ? hi.x : lo.x;  a[r].y     = cb ? hi.y : lo.y;
            a[r + 4].x = cb ? lo.x : hi.x;  a[r + 4].y = cb ? lo.y : hi.y;
        }
    }
    // (5 -> 6): ctrl r bit 2, tgt r bit 1: swap 4<->6, 5<->7 (free register renames)
    swap2(a[4], a[6]); swap2(a[5], a[7]);
    // (6 -> 7): ctrl r bit 1, tgt r bit 0: swap 2<->3, 6<->7
    swap2(a[2], a[3]); swap2(a[6], a[7]);
    // (7 -> 0): ctrl r bit 0 (odd r), tgt lane bit 4: unconditional exchange for odd r
#pragma unroll
    for (int r = 1; r < 8; r += 2) {
        a[r].x = __shfl_xor_sync(FULL, a[r].x, 16);
        a[r].y = __shfl_xor_sync(FULL, a[r].y, 16);
    }
}

__device__ __forceinline__ float warp_sum(float v) {
#pragma unroll
    for (int m = 16; m; m >>= 1) v += __shfl_xor_sync(FULL, v, m);
    return v;
}

// ---------- statevector simulation: one warp per token ----------
__global__ void __launch_bounds__(256) qsim_kernel(const float* __restrict__ x,
                                                   const float* __restrict__ prx,
                                                   const float* __restrict__ prz) {
    __shared__ float rxc[16], rxs[16], rzc[16], rzs[16];
    int tid = threadIdx.x;
    if (tid < 16) {
        float s, c; sincosf(0.5f * prx[tid], &s, &c);
        rxs[tid] = s; rxc[tid] = c;
    } else if (tid < 32) {
        int i = tid - 16;
        float s, c; sincosf(0.5f * prz[i], &s, &c);
        rzs[i] = s; rzc[i] = c;
    }
    __syncthreads();

    int lane = tid & 31;
    int t = blockIdx.x * 8 + (tid >> 5);  // token index, contiguous 8 floats per token

    // Per-token data-encoding angles: lane w (<8) owns wire w's cos/sin of theta/2.
    float mc = 1.f, ms = 0.f;
    if (lane < 8) sincosf(0.5f * x[t * 8 + lane], &ms, &mc);

    // |0...0> : amplitude 1 at global index 0 (lane 0, r 0)
    float2 a[8];
#pragma unroll
    for (int r = 0; r < 8; r++) a[r] = mk2(0.f, 0.f);
    if (lane == 0) a[0].x = 1.f;

#define DATA_RX(w) { float c_ = __shfl_sync(FULL, mc, (w)); float s_ = __shfl_sync(FULL, ms, (w)); apply_rx<(w)>(a, c_, s_); }
    DATA_RX(0); DATA_RX(1); DATA_RX(2); DATA_RX(3);
    DATA_RX(4); DATA_RX(5); DATA_RX(6); DATA_RX(7);
#undef DATA_RX

#define PARAM(l, w) { apply_rx<(w)>(a, rxc[(l)*8+(w)], rxs[(l)*8+(w)]); \
                      apply_rz<(w)>(a, lane, rzc[(l)*8+(w)], rzs[(l)*8+(w)]); }
    PARAM(0,0); PARAM(0,1); PARAM(0,2); PARAM(0,3);
    PARAM(0,4); PARAM(0,5); PARAM(0,6); PARAM(0,7);
    cnot_chain(a, lane);
    PARAM(1,0); PARAM(1,1); PARAM(1,2); PARAM(1,3);
    PARAM(1,4); PARAM(1,5); PARAM(1,6); PARAM(1,7);
    cnot_chain(a, lane);
#undef PARAM

    // probabilities and PauliZ expectations
    float p[8];
#pragma unroll
    for (int r = 0; r < 8; r++) p[r] = a[r].x * a[r].x + a[r].y * a[r].y;
    float tp = ((p[0] + p[1]) + (p[2] + p[3])) + ((p[4] + p[5]) + (p[6] + p[7]));

    float res = 0.f;
    // wires 0..4: sign from lane bit (4-w)
#pragma unroll
    for (int w = 0; w < 5; w++) {
        float v = (lane & (1 << (4 - w))) ? -tp : tp;
        v = warp_sum(v);
        if (lane == w) res = v;
    }
    // wires 5,6,7: sign from r bits 2,1,0
    {
        float v = ((p[0] + p[1]) + (p[2] + p[3])) - ((p[4] + p[5]) + (p[6] + p[7]));
        v = warp_sum(v); if (lane == 5) res = v;
    }
    {
        float v = ((p[0] + p[1]) - (p[2] + p[3])) + ((p[4] + p[5]) - (p[6] + p[7]));
        v = warp_sum(v); if (lane == 6) res = v;
    }
    {
        float v = ((p[0] - p[1]) + (p[2] - p[3])) + ((p[4] - p[5]) + (p[6] - p[7]));
        v = warp_sum(v); if (lane == 7) res = v;
    }

    if (lane < 8) g_q[t * 8 + lane] = res;
}

// ---------- out = q @ W^T  (2048 x 64 @ 64 x 64) ----------
__global__ void __launch_bounds__(512) combine_kernel(const float* __restrict__ W,
                                                      float* __restrict__ out) {
    __shared__ float Ws[64 * 65];   // padded stride 65: conflict-free reads & writes
    __shared__ float qs[512];       // 8 rows of q
    int tid = threadIdx.x;
#pragma unroll
    for (int i = tid; i < 4096; i += 512) {
        int j = i >> 6, k = i & 63;
        Ws[j * 65 + k] = W[i];
    }
    qs[tid] = g_q[blockIdx.x * 512 + tid];
    __syncthreads();

    int lr = tid >> 6;      // local row 0..7
    int j  = tid & 63;      // output column
    const float* qrow = &qs[lr * 64];
    float acc = 0.f;
#pragma unroll
    for (int k = 0; k < 64; k++)
        acc = fmaf(qrow[k], Ws[j * 65 + k], acc);
    out[blockIdx.x * 512 + tid] = acc;
}

extern "C" void kernel_launch(void* const* d_in, const int* in_sizes, int n_in,
                              void* d_out, int out_size) {
    const float* x   = (const float*)d_in[0];
    const float* prx = (const float*)d_in[1];
    const float* prz = (const float*)d_in[2];
    const float* W   = (const float*)d_in[3];
    float* out = (float*)d_out;

    int n_tok = in_sizes[0] / 8;                 // 16384 tokens (one warp each)
    qsim_kernel<<<n_tok / 8, 256>>>(x, prx, prz);  // 2048 blocks x 8 warps
    combine_kernel<<<in_sizes[0] / 512, 512>>>(W, out);  // 256 blocks
}

// round 2
// speedup vs baseline: 1.2977x; 1.2977x over previous
#include <cuda_runtime.h>

#define FULL 0xffffffffu
typedef unsigned long long ull;

// ---------- f32x2 packed helpers (sm_100+) ----------
__device__ __forceinline__ ull pk(float lo, float hi) {
    ull r; asm("mov.b64 %0, {%1,%2};" : "=l"(r) : "f"(lo), "f"(hi)); return r;
}
__device__ __forceinline__ void upk(ull v, float &lo, float &hi) {
    asm("mov.b64 {%0,%1}, %2;" : "=f"(lo), "=f"(hi) : "l"(v));
}
__device__ __forceinline__ ull f2fma(ull a, ull b, ull c) {
    ull d; asm("fma.rn.f32x2 %0,%1,%2,%3;" : "=l"(d) : "l"(a), "l"(b), "l"(c)); return d;
}
__device__ __forceinline__ ull f2mul(ull a, ull b) {
    ull d; asm("mul.rn.f32x2 %0,%1,%2;" : "=l"(d) : "l"(a), "l"(b)); return d;
}
__device__ __forceinline__ ull swph(ull v) { float lo, hi; upk(v, lo, hi); return pk(hi, lo); }

// State: 256 amps over 32 lanes x 8 per-thread. Amp index i = lane*8 + r.
// Packs: X[k]/Y[k] hold re/im of amps r=2k (lo half) and r=2k+1 (hi half).
// Wire w acts on bit p = 7-w: p>=3 -> lane bit (p-3); p=2,1 -> pack pairs; p=0 -> in-pack halves.

// RX: new = c*a + s*(partner.y, -partner.x)   [matrix [[c,-is],[-is,c]]], symmetric in the pair.
template <int W>
__device__ __forceinline__ void apply_rx(ull X[4], ull Y[4], float cc, float ss) {
    ull c2 = pk(cc, cc), s2 = pk(ss, ss), n2 = pk(-ss, -ss);
    if constexpr (W <= 4) {
        const int m = 16 >> W;
#pragma unroll
        for (int k = 0; k < 4; k++) {
            ull px = __shfl_xor_sync(FULL, X[k], m);
            ull py = __shfl_xor_sync(FULL, Y[k], m);
            X[k] = f2fma(c2, X[k], f2mul(s2, py));
            Y[k] = f2fma(c2, Y[k], f2mul(n2, px));
        }
    } else if constexpr (W == 5) {  // partner pack k <-> k+2
#pragma unroll
        for (int k = 0; k < 2; k++) {
            ull x0 = X[k], x1 = X[k + 2], y0 = Y[k], y1 = Y[k + 2];
            X[k]     = f2fma(c2, x0, f2mul(s2, y1));
            X[k + 2] = f2fma(c2, x1, f2mul(s2, y0));
            Y[k]     = f2fma(c2, y0, f2mul(n2, x1));
            Y[k + 2] = f2fma(c2, y1, f2mul(n2, x0));
        }
    } else if constexpr (W == 6) {  // partner pack k <-> k+1
#pragma unroll
        for (int k = 0; k < 4; k += 2) {
            ull x0 = X[k], x1 = X[k + 1], y0 = Y[k], y1 = Y[k + 1];
            X[k]     = f2fma(c2, x0, f2mul(s2, y1));
            X[k + 1] = f2fma(c2, x1, f2mul(s2, y0));
            Y[k]     = f2fma(c2, y0, f2mul(n2, x1));
            Y[k + 1] = f2fma(c2, y1, f2mul(n2, x0));
        }
    } else {  // W==7: partner = other half of the same pack
#pragma unroll
        for (int k = 0; k < 4; k++) {
            ull xs = swph(X[k]), ys = swph(Y[k]);
            X[k] = f2fma(c2, X[k], f2mul(s2, ys));
            Y[k] = f2fma(c2, Y[k], f2mul(n2, xs));
        }
    }
}

// RZ: bit==0 -> mult by (c - i s): nx = c*x + s*y, ny = c*y - s*x ; bit==1 opposite sign.
// se = bit ? s : -s ;  nx = c*x - se*y ; ny = c*y + se*x
template <int W>
__device__ __forceinline__ void apply_rz(ull X[4], ull Y[4], int lane, float cc, float ss) {
    ull c2 = pk(cc, cc);
    if constexpr (W <= 4) {
        float se = (lane & (16 >> W)) ? ss : -ss;
        ull sv = pk(se, se), nv = pk(-se, -se);
#pragma unroll
        for (int k = 0; k < 4; k++) {
            ull ox = X[k];
            X[k] = f2fma(c2, X[k], f2mul(nv, Y[k]));
            Y[k] = f2fma(c2, Y[k], f2mul(sv, ox));
        }
    } else if constexpr (W == 5) {  // r bit2: packs 0,1 -> -s ; 2,3 -> +s
        ull sp = pk(ss, ss), sn = pk(-ss, -ss);
#pragma unroll
        for (int k = 0; k < 4; k++) {
            ull sv = (k < 2) ? sn : sp, nv = (k < 2) ? sp : sn;
            ull ox = X[k];
            X[k] = f2fma(c2, X[k], f2mul(nv, Y[k]));
            Y[k] = f2fma(c2, Y[k], f2mul(sv, ox));
        }
    } else if constexpr (W == 6) {  // r bit1: packs 0,2 -> -s ; 1,3 -> +s
        ull sp = pk(ss, ss), sn = pk(-ss, -ss);
#pragma unroll
        for (int k = 0; k < 4; k++) {
            ull sv = (k & 1) ? sp : sn, nv = (k & 1) ? sn : sp;
            ull ox = X[k];
            X[k] = f2fma(c2, X[k], f2mul(nv, Y[k]));
            Y[k] = f2fma(c2, Y[k], f2mul(sv, ox));
        }
    } else {  // W==7: r bit0: lo -> -s, hi -> +s
        ull sv = pk(-ss, ss), nv = pk(ss, -ss);
#pragma unroll
        for (int k = 0; k < 4; k++) {
            ull ox = X[k];
            X[k] = f2fma(c2, X[k], f2mul(nv, Y[k]));
            Y[k] = f2fma(c2, Y[k], f2mul(sv, ox));
        }
    }
}

// CNOT chain (0->1),(1->2),(2->3),(3->4),(4->5),(5->6),(6->7),(7->0).
// The four lane-bit CNOTs compose into ONE lane permutation: j = lane ^ ((lane>>1)&15).
// If fold_last, skip (7->0) (odd-r lane^16 exchange) — folded into the measurement.
__device__ __forceinline__ void cnot_chain(ull X[4], ull Y[4], int lane, bool fold_last) {
    int j = lane ^ ((lane >> 1) & 15);
#pragma unroll
    for (int k = 0; k < 4; k++) {
        X[k] = __shfl_sync(FULL, X[k], j);
        Y[k] = __shfl_sync(FULL, Y[k], j);
    }
    // (4->5): ctrl lane bit0, tgt r bit2: swap packs (0,2),(1,3) when lane odd
    bool cb = lane & 1;
    {
        ull t;
        t = cb ? X[2] : X[0]; X[2] = cb ? X[0] : X[2]; X[0] = t;
        t = cb ? X[3] : X[1]; X[3] = cb ? X[1] : X[3]; X[1] = t;
        t = cb ? Y[2] : Y[0]; Y[2] = cb ? Y[0] : Y[2]; Y[0] = t;
        t = cb ? Y[3] : Y[1]; Y[3] = cb ? Y[1] : Y[3]; Y[1] = t;
    }
    // (5->6): swap pack2 <-> pack3 (pure rename)
    { ull t = X[2]; X[2] = X[3]; X[3] = t; t = Y[2]; Y[2] = Y[3]; Y[3] = t; }
    // (6->7): swap halves of pack1 and pack3
    X[1] = swph(X[1]); Y[1] = swph(Y[1]);
    X[3] = swph(X[3]); Y[3] = swph(Y[3]);
    // (7->0): odd-r amps exchange with lane^16
    if (!fold_last) {
#pragma unroll
        for (int k = 0; k < 4; k++) {
            float lo, hi;
            upk(X[k], lo, hi); hi = __shfl_xor_sync(FULL, hi, 16); X[k] = pk(lo, hi);
            upk(Y[k], lo, hi); hi = __shfl_xor_sync(FULL, hi, 16); Y[k] = pk(lo, hi);
        }
    }
}

// ---------- fused kernel: one block = one (b,s) row; warp h = head h ----------
__global__ void __launch_bounds__(256) qmha_kernel(const float* __restrict__ x,
                                                   const float* __restrict__ prx,
                                                   const float* __restrict__ prz,
                                                   const float* __restrict__ W,
                                                   float* __restrict__ out) {
    __shared__ float rxc[16], rxs[16], rzc[16], rzs[16];
    __shared__ float qs[64];
    int tid = threadIdx.x;
    if (tid < 16) {
        float s, c; sincosf(0.5f * prx[tid], &s, &c);
        rxs[tid] = s; rxc[tid] = c;
    } else if (tid < 32) {
        int i = tid - 16;
        float s, c; sincosf(0.5f * prz[i], &s, &c);
        rzs[i] = s; rzc[i] = c;
    }
    __syncthreads();

    int lane = tid & 31;
    int h = tid >> 5;
    // Token for this warp: x's natural 8-float block at blk*64 + h*8 (wires contiguous).
    float mc = 1.f, ms = 0.f;
    if (lane < 8) sincosf(0.5f * x[blockIdx.x * 64 + h * 8 + lane], &ms, &mc);

    float cw[8], sw[8];
#pragma unroll
    for (int w = 0; w < 8; w++) {
        cw[w] = __shfl_sync(FULL, mc, w);
        sw[w] = __shfl_sync(FULL, ms, w);
    }

    // Closed-form product state after data-encoding RX layer:
    // amp(i) = [prod_w (bit_w(i) ? s_w : c_w)] * (-i)^popcount(i)
    float ml = ((lane & 16) ? sw[0] : cw[0]) * ((lane & 8) ? sw[1] : cw[1]);
    ml *= ((lane & 4) ? sw[2] : cw[2]);
    ml *= ((lane & 2) ? sw[3] : cw[3]) * ((lane & 1) ? sw[4] : cw[4]);
    float t00 = cw[6] * cw[7], t01 = cw[6] * sw[7], t10 = sw[6] * cw[7], t11 = sw[6] * sw[7];
    float mr[8];
    mr[0] = cw[5] * t00; mr[1] = cw[5] * t01; mr[2] = cw[5] * t10; mr[3] = cw[5] * t11;
    mr[4] = sw[5] * t00; mr[5] = sw[5] * t01; mr[6] = sw[5] * t10; mr[7] = sw[5] * t11;

    const int pcr[8] = {0, 1, 1, 2, 1, 2, 2, 3};
    int Kl = __popc(lane);
    float ax[8], ay[8];
#pragma unroll
    for (int r = 0; r < 8; r++) {
        float m = ml * mr[r];
        int K = (Kl + pcr[r]) & 3;
        ax[r] = (K == 0) ? m : ((K == 2) ? -m : 0.f);
        ay[r] = (K == 3) ? m : ((K == 1) ? -m : 0.f);
    }
    ull X[4], Y[4];
#pragma unroll
    for (int k = 0; k < 4; k++) {
        X[k] = pk(ax[2 * k], ax[2 * k + 1]);
        Y[k] = pk(ay[2 * k], ay[2 * k + 1]);
    }

#define PGATE(l, w) { apply_rx<(w)>(X, Y, rxc[(l)*8+(w)], rxs[(l)*8+(w)]); \
                      apply_rz<(w)>(X, Y, lane, rzc[(l)*8+(w)], rzs[(l)*8+(w)]); }
    PGATE(0,0); PGATE(0,1); PGATE(0,2); PGATE(0,3);
    PGATE(0,4); PGATE(0,5); PGATE(0,6); PGATE(0,7);
    cnot_chain(X, Y, lane, false);
    PGATE(1,0); PGATE(1,1); PGATE(1,2); PGATE(1,3);
    PGATE(1,4); PGATE(1,5); PGATE(1,6); PGATE(1,7);
    cnot_chain(X, Y, lane, true);   // (7->0) folded into measurement below
#undef PGATE

    // probabilities
    float p[8];
#pragma unroll
    for (int k = 0; k < 4; k++) {
        ull P = f2fma(Y[k], Y[k], f2mul(X[k], X[k]));
        upk(P, p[2 * k], p[2 * k + 1]);
    }
    float pe = (p[0] + p[2]) + (p[4] + p[6]);   // even r (lo halves)
    float po = (p[1] + p[3]) + (p[5] + p[7]);   // odd r
    float tp = pe + po;
    float d  = pe - po;                          // wire7 sign pattern; also wire0 (folded (7->0))
    float v5 = ((p[0] + p[1]) + (p[2] + p[3])) - ((p[4] + p[5]) + (p[6] + p[7]));  // r bit2
    float v6 = ((p[0] + p[1]) + (p[4] + p[5])) - ((p[2] + p[3]) + (p[6] + p[7]));  // r bit1

    // Walsh butterfly on tp -> coefficient for mask M lands on lane M (wires 1-4 need M=8,4,2,1)
    float wht = tp;
#pragma unroll
    for (int m = 16; m >= 1; m >>= 1) {
        float t = __shfl_xor_sync(FULL, wht, m);
        wht = (lane & m) ? (t - wht) : (wht + t);
    }
    // d: need signed-by-bit4 sum (wire0, folded) and plain sum (wire7)
    float t16 = __shfl_xor_sync(FULL, d, 16);
    float e = d - t16;      // valid on bit4==0 lanes after plain sums
    float dsum = d + t16;
    v5 += __shfl_xor_sync(FULL, v5, 16);
    v6 += __shfl_xor_sync(FULL, v6, 16);
#pragma unroll
    for (int m = 8; m >= 1; m >>= 1) {
        e    += __shfl_xor_sync(FULL, e, m);
        dsum += __shfl_xor_sync(FULL, dsum, m);
        v5   += __shfl_xor_sync(FULL, v5, m);
        v6   += __shfl_xor_sync(FULL, v6, m);
    }
    float g = __shfl_sync(FULL, wht, (16 >> lane) & 31);  // lane w in 1..4 <- lane (16>>w)

    float res = (lane == 0) ? e
              : (lane < 5)  ? g
              : (lane == 5) ? v5
              : (lane == 6) ? v6 : dsum;
    if (lane < 8) qs[h * 8 + lane] = res;
    __syncthreads();

    // out[blk*64 + j] = sum_k qs[k] * W[j*64 + k], 4-way split-k per output
    int jj = tid >> 2, part = tid & 3;
    const float4* w4 = reinterpret_cast<const float4*>(W + jj * 64 + part * 16);
    const float* qp = qs + part * 16;
    float acc = 0.f;
#pragma unroll
    for (int i = 0; i < 4; i++) {
        float4 wv = __ldg(w4 + i);
        acc += qp[4 * i] * wv.x + qp[4 * i + 1] * wv.y + qp[4 * i + 2] * wv.z + qp[4 * i + 3] * wv.w;
    }
    acc += __shfl_xor_sync(FULL, acc, 1);
    acc += __shfl_xor_sync(FULL, acc, 2);
    if (part == 0) out[blockIdx.x * 64 + jj] = acc;
}

extern "C" void kernel_launch(void* const* d_in, const int* in_sizes, int n_in,
                              void* d_out, int out_size) {
    const float* x   = (const float*)d_in[0];
    const float* prx = (const float*)d_in[1];
    const float* prz = (const float*)d_in[2];
    const float* W   = (const float*)d_in[3];
    float* out = (float*)d_out;

    int n_rows = in_sizes[0] / 64;  // B*S = 2048 blocks, one (b,s) row each
    qmha_kernel<<<n_rows, 256>>>(x, prx, prz, W, out);
}

// round 3
// speedup vs baseline: 1.4361x; 1.1067x over previous
#include <cuda_runtime.h>

#define FULL 0xffffffffu
typedef unsigned long long ull;

// ---------- f32x2 packed helpers (sm_100+) ----------
__device__ __forceinline__ ull pk(float lo, float hi) {
    ull r; asm("mov.b64 %0, {%1,%2};" : "=l"(r) : "f"(lo), "f"(hi)); return r;
}
__device__ __forceinline__ void upk(ull v, float &lo, float &hi) {
    asm("mov.b64 {%0,%1}, %2;" : "=f"(lo), "=f"(hi) : "l"(v));
}
__device__ __forceinline__ ull f2fma(ull a, ull b, ull c) {
    ull d; asm("fma.rn.f32x2 %0,%1,%2,%3;" : "=l"(d) : "l"(a), "l"(b), "l"(c)); return d;
}
__device__ __forceinline__ ull f2mul(ull a, ull b) {
    ull d; asm("mul.rn.f32x2 %0,%1,%2;" : "=l"(d) : "l"(a), "l"(b)); return d;
}
__device__ __forceinline__ ull swph(ull v) { float lo, hi; upk(v, lo, hi); return pk(hi, lo); }

// State: 256 amps over 32 lanes x 8 per-thread. Amp index i = lane*8 + r.
// Index bits: i7..i3 = lane bits l4..l0, i2..i0 = r bits. Wire w <-> index bit i(7-w).

// RX: new = c*a + s*(py, -px), symmetric within the pair.
template <int W>
__device__ __forceinline__ void apply_rx(ull X[4], ull Y[4], float cc, float ss) {
    ull c2 = pk(cc, cc), s2 = pk(ss, ss), n2 = pk(-ss, -ss);
    if constexpr (W <= 4) {
        const int m = 16 >> W;
#pragma unroll
        for (int k = 0; k < 4; k++) {
            ull px = __shfl_xor_sync(FULL, X[k], m);
            ull py = __shfl_xor_sync(FULL, Y[k], m);
            X[k] = f2fma(c2, X[k], f2mul(s2, py));
            Y[k] = f2fma(c2, Y[k], f2mul(n2, px));
        }
    } else if constexpr (W == 5) {  // partner pack k <-> k+2
#pragma unroll
        for (int k = 0; k < 2; k++) {
            ull x0 = X[k], x1 = X[k + 2], y0 = Y[k], y1 = Y[k + 2];
            X[k]     = f2fma(c2, x0, f2mul(s2, y1));
            X[k + 2] = f2fma(c2, x1, f2mul(s2, y0));
            Y[k]     = f2fma(c2, y0, f2mul(n2, x1));
            Y[k + 2] = f2fma(c2, y1, f2mul(n2, x0));
        }
    } else if constexpr (W == 6) {  // partner pack k <-> k+1
#pragma unroll
        for (int k = 0; k < 4; k += 2) {
            ull x0 = X[k], x1 = X[k + 1], y0 = Y[k], y1 = Y[k + 1];
            X[k]     = f2fma(c2, x0, f2mul(s2, y1));
            X[k + 1] = f2fma(c2, x1, f2mul(s2, y0));
            Y[k]     = f2fma(c2, y0, f2mul(n2, x1));
            Y[k + 1] = f2fma(c2, y1, f2mul(n2, x0));
        }
    } else {  // W==7: partner = other half of the same pack
#pragma unroll
        for (int k = 0; k < 4; k++) {
            ull xs = swph(X[k]), ys = swph(Y[k]);
            X[k] = f2fma(c2, X[k], f2mul(s2, ys));
            Y[k] = f2fma(c2, Y[k], f2mul(n2, xs));
        }
    }
}

// RZ: se = bit ? s : -s ;  nx = c*x - se*y ; ny = c*y + se*x
template <int W>
__device__ __forceinline__ void apply_rz(ull X[4], ull Y[4], int lane, float cc, float ss) {
    ull c2 = pk(cc, cc);
    if constexpr (W <= 4) {
        float se = (lane & (16 >> W)) ? ss : -ss;
        ull sv = pk(se, se), nv = pk(-se, -se);
#pragma unroll
        for (int k = 0; k < 4; k++) {
            ull ox = X[k];
            X[k] = f2fma(c2, X[k], f2mul(nv, Y[k]));
            Y[k] = f2fma(c2, Y[k], f2mul(sv, ox));
        }
    } else if constexpr (W == 5) {  // r bit2: packs 0,1 -> -s ; 2,3 -> +s
        ull sp = pk(ss, ss), sn = pk(-ss, -ss);
#pragma unroll
        for (int k = 0; k < 4; k++) {
            ull sv = (k < 2) ? sn : sp, nv = (k < 2) ? sp : sn;
            ull ox = X[k];
            X[k] = f2fma(c2, X[k], f2mul(nv, Y[k]));
            Y[k] = f2fma(c2, Y[k], f2mul(sv, ox));
        }
    } else if constexpr (W == 6) {  // r bit1: packs 0,2 -> -s ; 1,3 -> +s
        ull sp = pk(ss, ss), sn = pk(-ss, -ss);
#pragma unroll
        for (int k = 0; k < 4; k++) {
            ull sv = (k & 1) ? sp : sn, nv = (k & 1) ? sn : sp;
            ull ox = X[k];
            X[k] = f2fma(c2, X[k], f2mul(nv, Y[k]));
            Y[k] = f2fma(c2, Y[k], f2mul(sv, ox));
        }
    } else {  // W==7: r bit0: lo -> -s, hi -> +s
        ull sv = pk(-ss, ss), nv = pk(ss, -ss);
#pragma unroll
        for (int k = 0; k < 4; k++) {
            ull ox = X[k];
            X[k] = f2fma(c2, X[k], f2mul(nv, Y[k]));
            Y[k] = f2fma(c2, Y[k], f2mul(sv, ox));
        }
    }
}

// CNOT chain (0->1),...,(6->7),(7->0), applied physically (needed before L1 RX).
// Lane-bit CNOTs compose into one lane permutation j = lane ^ ((lane>>1)&15).
__device__ __forceinline__ void cnot_chain(ull X[4], ull Y[4], int lane) {
    int j = lane ^ ((lane >> 1) & 15);
#pragma unroll
    for (int k = 0; k < 4; k++) {
        X[k] = __shfl_sync(FULL, X[k], j);
        Y[k] = __shfl_sync(FULL, Y[k], j);
    }
    // (4->5): ctrl lane bit0, tgt r bit2: swap packs (0,2),(1,3) when lane odd
    bool cb = lane & 1;
    {
        ull t;
        t = cb ? X[2] : X[0]; X[2] = cb ? X[0] : X[2]; X[0] = t;
        t = cb ? X[3] : X[1]; X[3] = cb ? X[1] : X[3]; X[1] = t;
        t = cb ? Y[2] : Y[0]; Y[2] = cb ? Y[0] : Y[2]; Y[0] = t;
        t = cb ? Y[3] : Y[1]; Y[3] = cb ? Y[1] : Y[3]; Y[1] = t;
    }
    // (5->6): swap pack2 <-> pack3 (rename)
    { ull t = X[2]; X[2] = X[3]; X[3] = t; t = Y[2]; Y[2] = Y[3]; Y[3] = t; }
    // (6->7): swap halves of pack1 and pack3
    X[1] = swph(X[1]); Y[1] = swph(Y[1]);
    X[3] = swph(X[3]); Y[3] = swph(Y[3]);
    // (7->0): odd-r amps exchange with lane^16
#pragma unroll
    for (int k = 0; k < 4; k++) {
        float lo, hi;
        upk(X[k], lo, hi); hi = __shfl_xor_sync(FULL, hi, 16); X[k] = pk(lo, hi);
        upk(Y[k], lo, hi); hi = __shfl_xor_sync(FULL, hi, 16); Y[k] = pk(lo, hi);
    }
}

// ---------- fused kernel: one block = one (b,s) row; warp h = head h ----------
__global__ void __launch_bounds__(256) qmha_kernel(const float* __restrict__ x,
                                                   const float* __restrict__ prx,
                                                   const float* __restrict__ prz,
                                                   const float* __restrict__ W,
                                                   float* __restrict__ out) {
    __shared__ float rz0c[8], rz0s[8], rx1c[8], rx1s[8];
    __shared__ float qs[64];
    int tid = threadIdx.x;
    if (tid < 8) {            // layer-0 RZ params
        float s, c; sincosf(0.5f * prz[tid], &s, &c);
        rz0s[tid] = s; rz0c[tid] = c;
    } else if (tid < 16) {    // layer-1 RX params
        int i = tid - 8;
        float s, c; sincosf(0.5f * prx[8 + i], &s, &c);
        rx1s[i] = s; rx1c[i] = c;
    }
    // layer-0 RX merges into data encoding; layer-1 RZ is dropped (phases before a
    // permutation + |amp|^2 are unobservable).
    __syncthreads();

    int lane = tid & 31;
    int h = tid >> 5;
    // Merged data+L0 RX angle per wire: (x_w + prx[0,w]) / 2
    float mc = 1.f, ms = 0.f;
    if (lane < 8) sincosf(0.5f * (x[blockIdx.x * 64 + h * 8 + lane] + prx[lane]), &ms, &mc);

    float cw[8], sw[8];
#pragma unroll
    for (int w = 0; w < 8; w++) {
        cw[w] = __shfl_sync(FULL, mc, w);
        sw[w] = __shfl_sync(FULL, ms, w);
    }

    // Product state after merged RX layer: amp(i) = [prod_w (bit_w ? s_w : c_w)] * (-i)^popcount(i)
    float ml = ((lane & 16) ? sw[0] : cw[0]) * ((lane & 8) ? sw[1] : cw[1]);
    ml *= ((lane & 4) ? sw[2] : cw[2]);
    ml *= ((lane & 2) ? sw[3] : cw[3]) * ((lane & 1) ? sw[4] : cw[4]);
    float t00 = cw[6] * cw[7], t01 = cw[6] * sw[7], t10 = sw[6] * cw[7], t11 = sw[6] * sw[7];
    float mr[8];
    mr[0] = cw[5] * t00; mr[1] = cw[5] * t01; mr[2] = cw[5] * t10; mr[3] = cw[5] * t11;
    mr[4] = sw[5] * t00; mr[5] = sw[5] * t01; mr[6] = sw[5] * t10; mr[7] = sw[5] * t11;

    const int pcr[8] = {0, 1, 1, 2, 1, 2, 2, 3};
    int Kl = __popc(lane);
    float ax[8], ay[8];
#pragma unroll
    for (int r = 0; r < 8; r++) {
        float m = ml * mr[r];
        int K = (Kl + pcr[r]) & 3;
        ax[r] = (K == 0) ? m : ((K == 2) ? -m : 0.f);
        ay[r] = (K == 3) ? m : ((K == 1) ? -m : 0.f);
    }
    ull X[4], Y[4];
#pragma unroll
    for (int k = 0; k < 4; k++) {
        X[k] = pk(ax[2 * k], ax[2 * k + 1]);
        Y[k] = pk(ay[2 * k], ay[2 * k + 1]);
    }

    // Layer 0: RZ only (RX merged into init)
    apply_rz<0>(X, Y, lane, rz0c[0], rz0s[0]);
    apply_rz<1>(X, Y, lane, rz0c[1], rz0s[1]);
    apply_rz<2>(X, Y, lane, rz0c[2], rz0s[2]);
    apply_rz<3>(X, Y, lane, rz0c[3], rz0s[3]);
    apply_rz<4>(X, Y, lane, rz0c[4], rz0s[4]);
    apply_rz<5>(X, Y, lane, rz0c[5], rz0s[5]);
    apply_rz<6>(X, Y, lane, rz0c[6], rz0s[6]);
    apply_rz<7>(X, Y, lane, rz0c[7], rz0s[7]);

    cnot_chain(X, Y, lane);

    // Layer 1: RX only (RZ dropped)
    apply_rx<0>(X, Y, rx1c[0], rx1s[0]);
    apply_rx<1>(X, Y, rx1c[1], rx1s[1]);
    apply_rx<2>(X, Y, rx1c[2], rx1s[2]);
    apply_rx<3>(X, Y, rx1c[3], rx1s[3]);
    apply_rx<4>(X, Y, rx1c[4], rx1s[4]);
    apply_rx<5>(X, Y, rx1c[5], rx1s[5]);
    apply_rx<6>(X, Y, rx1c[6], rx1s[6]);
    apply_rx<7>(X, Y, rx1c[7], rx1s[7]);

    // Second CNOT chain folded into measurement: post-chain bit k = prefix-XOR of
    // wires 0..k (bit0 = XOR of wires 1..7). Wire-k <Z> = Walsh coeff of probs at:
    //   w1..w4: lane masks 24,28,30,31 (r-mask 0)
    //   w5: lane 31, r-mask 4 ; w6: lane 31, r-mask 6 ; w7: lane 31, r-mask 7
    //   w0: lane 15, r-mask 7
    float p[8];
#pragma unroll
    for (int k = 0; k < 4; k++) {
        ull P = f2fma(Y[k], Y[k], f2mul(X[k], X[k]));
        upk(P, p[2 * k], p[2 * k + 1]);
    }
    float a01 = p[0] + p[1], d01 = p[0] - p[1];
    float a23 = p[2] + p[3], d23 = p[2] - p[3];
    float a45 = p[4] + p[5], d45 = p[4] - p[5];
    float a67 = p[6] + p[7], d67 = p[6] - p[7];
    float S = (a01 + a23) + (a45 + a67);          // r-mask 0
    float A = (a01 + a23) - (a45 + a67);          // r-mask 4 (sign by r bit2)
    float B = (a01 - a23) - (a45 - a67);          // r-mask 6 (sign by r bit2^bit1)
    float C = (d01 - d23) + (d67 - d45);          // r-mask 7 (sign by parity(r))

    // Full WHT butterfly on S: coeff at lane-mask M lands on lane M
    float wht = S;
#pragma unroll
    for (int m = 16; m >= 1; m >>= 1) {
        float t = __shfl_xor_sync(FULL, wht, m);
        wht = (lane & m) ? (t - wht) : (wht + t);
    }
    // lanes 1..4 pick masks 24,28,30,31
    float g = __shfl_sync(FULL, wht, (32 - (16 >> lane)) & 31);

    // Uniform full-lane-mask signed sums for A, B
#pragma unroll
    for (int m = 16; m >= 1; m >>= 1) {
        float tA = __shfl_xor_sync(FULL, A, m);
        float tB = __shfl_xor_sync(FULL, B, m);
        A = (lane & m) ? (tA - A) : (A - tA);
        B = (lane & m) ? (tB - B) : (B - tB);
    }
    // C: signed reduce over l3..l0, then combine across l4 both ways
#pragma unroll
    for (int m = 8; m >= 1; m >>= 1) {
        float tC = __shfl_xor_sync(FULL, C, m);
        C = (lane & m) ? (tC - C) : (C - tC);
    }
    float t16 = __shfl_xor_sync(FULL, C, 16);
    float w0v = C + t16;                               // lane mask 15 (wire 0)
    float w7v = (lane & 16) ? (t16 - C) : (C - t16);   // lane mask 31 (wire 7)

    float res = (lane == 0) ? w0v
              : (lane < 5)  ? g
              : (lane == 5) ? A
              : (lane == 6) ? B : w7v;
    if (lane < 8) qs[h * 8 + lane] = res;
    __syncthreads();

    // out[blk*64 + j] = sum_k qs[k] * W[j*64 + k], 4-way split-k per output
    int jj = tid >> 2, part = tid & 3;
    const float4* w4 = reinterpret_cast<const float4*>(W + jj * 64 + part * 16);
    const float* qp = qs + part * 16;
    float acc = 0.f;
#pragma unroll
    for (int i = 0; i < 4; i++) {
        float4 wv = __ldg(w4 + i);
        acc += qp[4 * i] * wv.x + qp[4 * i + 1] * wv.y + qp[4 * i + 2] * wv.z + qp[4 * i + 3] * wv.w;
    }
    acc += __shfl_xor_sync(FULL, acc, 1);
    acc += __shfl_xor_sync(FULL, acc, 2);
    if (part == 0) out[blockIdx.x * 64 + jj] = acc;
}

extern "C" void kernel_launch(void* const* d_in, const int* in_sizes, int n_in,
                              void* d_out, int out_size) {
    const float* x   = (const float*)d_in[0];
    const float* prx = (const float*)d_in[1];
    const float* prz = (const float*)d_in[2];
    const float* W   = (const float*)d_in[3];
    float* out = (float*)d_out;

    int n_rows = in_sizes[0] / 64;  // B*S = 2048 blocks, one (b,s) row each
    qmha_kernel<<<n_rows, 256>>>(x, prx, prz, W, out);
}

// round 4
// speedup vs baseline: 2.5421x; 1.7701x over previous
#include <cuda_runtime.h>

// Per-token qlayer outputs, [B*S*64] = 131072 floats.
__device__ float g_q[4 * 512 * 64];

// ===========================================================================
// Closed-form evaluation. Per token:
//   wire states after merged RX(theta)+RZ(phi):  z=cos(th), x=sin(th)sin(ph),
//   y=-sin(th)cos(ph).
//   Observables (chain2 folded): G_k = Z_0..Z_k (k>=1), G_0 = Z_1..Z_7,
//   conjugated through RX(gamma) layer then chain1, contracted against the
//   product state via a 4x4 Pauli transfer sweep:
//   A[q0][c] rows = pending wire-0 Pauli (I,X,Y,Z), cols = rolling carry.
//   Step w (gate CNOT(w,w+1), finalize wire w actively):
//     I' = c1*Z + s1*x*Y ;  X' = c1*x*Z + s1*Y
//     Y' = c1*y*I - s1*z*X ;  Z' = c1*z*I + s1*y*X      (x,y,z of wire w+1)
//   E_k (k=1..6) = (z_{k+2}*..*z_7) * ( s1_0*A_k[Y][Z] + c1_0*A_k[Z][Z] )
//   E_7 = c1_7*( s1_0*A6[Y][I] + c1_0*A6[Z][I] )
//       + s1_7*( c1_0*A6[Y][X] - s1_0*A6[Z][X] )
//   E_0 = c1_7*A6[I][Z] + s1_7*A6[X][Y]
// ===========================================================================
__global__ void __launch_bounds__(128) qsim_closed(const float* __restrict__ x,
                                                   const float* __restrict__ prx,
                                                   const float* __restrict__ prz) {
    __shared__ float s_rx0[8], s_sf[8], s_cf[8], s_c1[8], s_s1[8];
    int tid = threadIdx.x;
    if (tid < 8) {
        s_rx0[tid] = prx[tid];
        float s, c; sincosf(prz[tid], &s, &c);   // layer-0 RZ angle (full angle)
        s_sf[tid] = s; s_cf[tid] = c;
    } else if (tid < 16) {
        int i = tid - 8;
        float s, c; sincosf(prx[8 + i], &s, &c); // layer-1 RX angle (full angle)
        s_s1[i] = s; s_c1[i] = c;
    }
    __syncthreads();

    int t = blockIdx.x * 128 + tid;
    const float4* xp = reinterpret_cast<const float4*>(x + t * 8);
    float4 xa = __ldg(xp), xb = __ldg(xp + 1);
    float xv[8] = {xa.x, xa.y, xa.z, xa.w, xb.x, xb.y, xb.z, xb.w};

    float vx[8], vy[8], vz[8];
#pragma unroll
    for (int w = 0; w < 8; w++) {
        float st, ct; sincosf(xv[w] + s_rx0[w], &st, &ct);
        vz[w] = ct;
        vx[w] = st * s_sf[w];
        vy[w] = -st * s_cf[w];
    }

    // A_0: state after gate CNOT(0,1) (closed form from the CNOT Pauli table)
    float A[4][4];
    A[0][0] = 1.f;            A[0][1] = vx[1];          A[0][2] = vz[0] * vy[1];  A[0][3] = vz[0] * vz[1];
    A[1][0] = vx[0] * vx[1];  A[1][1] = vx[0];          A[1][2] = vy[0] * vz[1];  A[1][3] = -vy[0] * vy[1];
    A[2][0] = vy[0] * vx[1];  A[2][1] = vy[0];          A[2][2] = -vx[0] * vz[1]; A[2][3] = vx[0] * vy[1];
    A[3][0] = vz[0];          A[3][1] = vz[0] * vx[1];  A[3][2] = vy[1];          A[3][3] = vz[1];

    // Suffix z-products for the inactive tails: Zt[k] = prod_{j=k+2..7} vz[j]
    float Zt[7];
    Zt[6] = 1.f;
#pragma unroll
    for (int k = 5; k >= 1; k--) Zt[k] = Zt[k + 1] * vz[k + 2];

    float q[8];
    float c10 = s_c1[0], s10 = s_s1[0];
#pragma unroll
    for (int w = 1; w <= 6; w++) {
        float cc = s_c1[w], ss = s_s1[w];
        float xn = vx[w + 1], yn = vy[w + 1], zn = vz[w + 1];
        float cx = cc * xn, cy = cc * yn, cz = cc * zn;
        float sx = ss * xn, sy = ss * yn, sz = ss * zn;
#pragma unroll
        for (int r = 0; r < 4; r++) {
            float aI = A[r][0], aX = A[r][1], aY = A[r][2], aZ = A[r][3];
            A[r][0] = cc * aZ + sx * aY;
            A[r][1] = cx * aZ + ss * aY;
            A[r][2] = cy * aI - sz * aX;
            A[r][3] = cz * aI + sy * aX;
        }
        q[w] = Zt[w] * (s10 * A[2][3] + c10 * A[3][3]);
    }
    float c17 = s_c1[7], s17 = s_s1[7];
    q[7] = c17 * (s10 * A[2][0] + c10 * A[3][0]) + s17 * (c10 * A[2][1] - s10 * A[3][1]);
    q[0] = c17 * A[0][3] + s17 * A[1][2];

    float4* o = reinterpret_cast<float4*>(g_q + t * 8);
    o[0] = make_float4(q[0], q[1], q[2], q[3]);
    o[1] = make_float4(q[4], q[5], q[6], q[7]);
}

// ---------- out[row][j] = sum_k q[row][k] * W[j][k]  (2048 x 64 @ 64 x 64) ----
__global__ void __launch_bounds__(256) combine_kernel(const float* __restrict__ W,
                                                      float* __restrict__ out) {
    __shared__ float qs[256];   // 4 rows of q
    int tid = threadIdx.x;
    qs[tid] = g_q[blockIdx.x * 256 + tid];
    __syncthreads();

    int r = tid >> 6, j = tid & 63;
    const float4* w4 = reinterpret_cast<const float4*>(W + j * 64);
    const float* qp = qs + r * 64;
    float acc = 0.f;
#pragma unroll
    for (int i = 0; i < 16; i++) {
        float4 wv = __ldg(w4 + i);
        acc += qp[4 * i] * wv.x + qp[4 * i + 1] * wv.y
             + qp[4 * i + 2] * wv.z + qp[4 * i + 3] * wv.w;
    }
    out[blockIdx.x * 256 + tid] = acc;
}

extern "C" void kernel_launch(void* const* d_in, const int* in_sizes, int n_in,
                              void* d_out, int out_size) {
    const float* x   = (const float*)d_in[0];
    const float* prx = (const float*)d_in[1];
    const float* prz = (const float*)d_in[2];
    const float* W   = (const float*)d_in[3];
    float* out = (float*)d_out;

    int n_tok = in_sizes[0] / 8;                       // 16384 tokens
    qsim_closed<<<n_tok / 128, 128>>>(x, prx, prz);    // 128 blocks
    combine_kernel<<<in_sizes[0] / 256, 256>>>(W, out);// 512 blocks
}

// round 5
// speedup vs baseline: 5.2107x; 2.0498x over previous
#include <cuda_runtime.h>

// ===========================================================================
// Fully fused: closed-form qlayer (Pauli-transfer contraction, validated R4)
// + combine matmul with W staged in shared memory.
// Block b handles 8 (b,s) rows = 64 tokens. 256 blocks x 128 threads.
// ===========================================================================
__global__ void __launch_bounds__(128) qmha_fused(const float* __restrict__ x,
                                                  const float* __restrict__ prx,
                                                  const float* __restrict__ prz,
                                                  const float* __restrict__ W,
                                                  float* __restrict__ out) {
    __shared__ float s_rx0[8], s_sf[8], s_cf[8], s_c1[8], s_s1[8];
    __shared__ float Ws[64 * 68];   // W[j][k] at Ws[j*68+k]; pad 68 -> conflict-free
    __shared__ float qs[512];       // 8 rows x 64 (token-major layout coincides)

    int tid = threadIdx.x;
    if (tid < 8) {
        s_rx0[tid] = prx[tid];
        float s, c; sincosf(prz[tid], &s, &c);    // layer-0 RZ (full angle)
        s_sf[tid] = s; s_cf[tid] = c;
    } else if (tid < 16) {
        int i = tid - 8;
        float s, c; sincosf(prx[8 + i], &s, &c);  // layer-1 RX (full angle)
        s_s1[i] = s; s_c1[i] = c;
    }

    // Stage W coalesced: 1024 float4s, 8 per thread.
    const float4* Wg = reinterpret_cast<const float4*>(W);
#pragma unroll
    for (int i = 0; i < 8; i++) {
        int m = tid + i * 128;          // float4 index
        int j = m >> 4, c = m & 15;
        reinterpret_cast<float4*>(Ws)[j * 17 + c] = __ldg(Wg + m);
    }
    __syncthreads();

    // ---------------- Phase 1: closed-form q for 64 tokens ----------------
    if (tid < 64) {
        int t = blockIdx.x * 64 + tid;
        const float4* xp = reinterpret_cast<const float4*>(x + t * 8);
        float4 xa = __ldg(xp), xb = __ldg(xp + 1);
        float xv[8] = {xa.x, xa.y, xa.z, xa.w, xb.x, xb.y, xb.z, xb.w};

        float vx[8], vy[8], vz[8];
#pragma unroll
        for (int w = 0; w < 8; w++) {
            float st, ct; sincosf(xv[w] + s_rx0[w], &st, &ct);
            vz[w] = ct;
            vx[w] = st * s_sf[w];
            vy[w] = -st * s_cf[w];
        }

        // A_0: state after CNOT(0,1); rows = pending wire-0 Pauli, cols = carry
        float A[4][4];
        A[0][0] = 1.f;            A[0][1] = vx[1];          A[0][2] = vz[0] * vy[1];  A[0][3] = vz[0] * vz[1];
        A[1][0] = vx[0] * vx[1];  A[1][1] = vx[0];          A[1][2] = vy[0] * vz[1];  A[1][3] = -vy[0] * vy[1];
        A[2][0] = vy[0] * vx[1];  A[2][1] = vy[0];          A[2][2] = -vx[0] * vz[1]; A[2][3] = vx[0] * vy[1];
        A[3][0] = vz[0];          A[3][1] = vz[0] * vx[1];  A[3][2] = vy[1];          A[3][3] = vz[1];

        float Zt[7];
        Zt[6] = 1.f;
#pragma unroll
        for (int k = 5; k >= 1; k--) Zt[k] = Zt[k + 1] * vz[k + 2];

        float q[8];
        float c10 = s_c1[0], s10 = s_s1[0];
#pragma unroll
        for (int w = 1; w <= 6; w++) {
            float cc = s_c1[w], ss = s_s1[w];
            float xn = vx[w + 1], yn = vy[w + 1], zn = vz[w + 1];
            float cx = cc * xn, cy = cc * yn, cz = cc * zn;
            float sx = ss * xn, sy = ss * yn, sz = ss * zn;
#pragma unroll
            for (int r = 0; r < 4; r++) {
                float aI = A[r][0], aX = A[r][1], aY = A[r][2], aZ = A[r][3];
                A[r][0] = cc * aZ + sx * aY;
                A[r][1] = cx * aZ + ss * aY;
                A[r][2] = cy * aI - sz * aX;
                A[r][3] = cz * aI + sy * aX;
            }
            q[w] = Zt[w] * (s10 * A[2][3] + c10 * A[3][3]);
        }
        float c17 = s_c1[7], s17 = s_s1[7];
        q[7] = c17 * (s10 * A[2][0] + c10 * A[3][0]) + s17 * (c10 * A[2][1] - s10 * A[3][1]);
        q[0] = c17 * A[0][3] + s17 * A[1][2];

        // qs[tid*8 + w] == row-major [row_local=tid/8][k=(tid%8)*8+w]
        float4* qo = reinterpret_cast<float4*>(qs + tid * 8);
        qo[0] = make_float4(q[0], q[1], q[2], q[3]);
        qo[1] = make_float4(q[4], q[5], q[6], q[7]);
    }
    __syncthreads();

    // ---------------- Phase 2: out[r][j] = sum_k qs[r][k] * Ws[j][k] -------
    int j = tid & 63, half = tid >> 6;     // half selects rows 0-3 / 4-7
    const float4* wrow = reinterpret_cast<const float4*>(Ws) + j * 17;
    const float4* q4 = reinterpret_cast<const float4*>(qs) + half * 64;  // 4 rows x 16 chunks

    float acc0 = 0.f, acc1 = 0.f, acc2 = 0.f, acc3 = 0.f;
#pragma unroll
    for (int c = 0; c < 16; c++) {
        float4 wv = wrow[c];
        float4 a = q4[c];          // row half*4+0
        float4 b = q4[16 + c];     // row half*4+1
        float4 d = q4[32 + c];     // row half*4+2
        float4 e = q4[48 + c];     // row half*4+3
        acc0 = fmaf(a.x, wv.x, fmaf(a.y, wv.y, fmaf(a.z, wv.z, fmaf(a.w, wv.w, acc0))));
        acc1 = fmaf(b.x, wv.x, fmaf(b.y, wv.y, fmaf(b.z, wv.z, fmaf(b.w, wv.w, acc1))));
        acc2 = fmaf(d.x, wv.x, fmaf(d.y, wv.y, fmaf(d.z, wv.z, fmaf(d.w, wv.w, acc2))));
        acc3 = fmaf(e.x, wv.x, fmaf(e.y, wv.y, fmaf(e.z, wv.z, fmaf(e.w, wv.w, acc3))));
    }
    int row0 = blockIdx.x * 8 + half * 4;
    out[(row0 + 0) * 64 + j] = acc0;
    out[(row0 + 1) * 64 + j] = acc1;
    out[(row0 + 2) * 64 + j] = acc2;
    out[(row0 + 3) * 64 + j] = acc3;
}

extern "C" void kernel_launch(void* const* d_in, const int* in_sizes, int n_in,
                              void* d_out, int out_size) {
    const float* x   = (const float*)d_in[0];
    const float* prx = (const float*)d_in[1];
    const float* prz = (const float*)d_in[2];
    const float* W   = (const float*)d_in[3];
    float* out = (float*)d_out;

    int n_rows = in_sizes[0] / 64;          // 2048 (b,s) rows
    qmha_fused<<<n_rows / 8, 128>>>(x, prx, prz, W, out);  // 256 blocks
}